// round 3
// baseline (speedup 1.0000x reference)
#include <cuda_runtime.h>

// MultiDense: y[b,n,o] = sum_i x[b,n,i] * A[n,o,i] + Bp[n,o]
// x:  (2048, 256, 256) fp32
// A:  (1, 256, 256, 256) fp32   (n, o, i)
// Bp: (1, 256, 256) fp32        (n, o)
// out:(2048, 256, 256) fp32

#define BSZ   2048
#define NSPL  256
#define DIN   256
#define DOUT  256

#define BM 64          // batch rows per block
#define BK 16
#define NSTAGE (DIN / BK)

// Xs row: 64 x-values duplicated as (x,x) pairs = 128 floats, chunk-swizzled.
// Chunk (16B) for (mg, h) lives at slot h*8+mg  ->  per-h LDS.128 across 8 mg
// hits 8 consecutive chunks = 128B, conflict-free, broadcast over og.
#define XPITCH 132
#define APITCH 260     // plain [k][o], 256 + 4 pad

typedef unsigned long long ull;

__device__ __forceinline__ ull pack_dup(float v) {
    ull r; asm("mov.b64 %0, {%1, %1};" : "=l"(r) : "f"(v)); return r;
}
__device__ __forceinline__ void ffma2(ull& c, ull a, ull b) {
    asm("fma.rn.f32x2 %0, %1, %2, %0;" : "+l"(c) : "l"(a), "l"(b));
}
__device__ __forceinline__ float2 unpack2(ull v) {
    float2 r; asm("mov.b64 {%0, %1}, %2;" : "=f"(r.x), "=f"(r.y) : "l"(v)); return r;
}

__global__ __launch_bounds__(256, 2)
void multidense_kernel(const float* __restrict__ x,
                       const float* __restrict__ A,
                       const float* __restrict__ Bp,
                       float* __restrict__ out)
{
    __shared__ float Xs[BK][XPITCH];
    __shared__ float As[BK][APITCH];

    const int tid   = threadIdx.x;
    const int n     = blockIdx.y;
    const int mBase = blockIdx.x * BM;

    // compute mapping: warp covers 64m x 32o; lane = mg*4 + og
    const int w   = tid >> 5;          // warp id: o base = w*32
    const int lid = tid & 31;
    const int mg  = lid >> 2;          // m group: rows mg*8 .. mg*8+7
    const int og  = lid & 3;           // o group: cols w*32 + og*8 .. +7
    const int oBase = w * 32 + og * 8;

    // loader mapping (unchanged): lr = m row 0..63, lq = k quad
    const int lr  = tid >> 2;
    const int lq  = tid & 3;
    // X store swizzle for row m=lr: chunk slot = h*8 + mgS, intra-chunk e*2
    const int mgS = lr >> 3;
    const int hS  = (lr & 7) >> 1;
    const int eS  = lr & 1;
    const int xoff = (hS * 8 + mgS) * 4 + 2 * eS;

    const float* xg = x + (size_t)(mBase + lr) * (NSPL * DIN) + (size_t)n * DIN + lq * 4;
    const float* Ag = A + (size_t)n * (DOUT * DIN) + (size_t)lr * DIN + lq * 4;

    ull acc[8][4];
    #pragma unroll
    for (int m = 0; m < 8; ++m) {
        acc[m][0] = 0ULL; acc[m][1] = 0ULL; acc[m][2] = 0ULL; acc[m][3] = 0ULL;
    }

    // prefetch stage 0
    float4 xr  = *(const float4*)(xg);
    float4 ar0 = *(const float4*)(Ag);
    float4 ar1 = *(const float4*)(Ag +  64 * DIN);
    float4 ar2 = *(const float4*)(Ag + 128 * DIN);
    float4 ar3 = *(const float4*)(Ag + 192 * DIN);

    for (int s = 0; s < NSTAGE; ++s) {
        __syncthreads();

        // X: duplicated pairs at swizzled chunk offsets
        *(ull*)&Xs[lq*4 + 0][xoff] = pack_dup(xr.x);
        *(ull*)&Xs[lq*4 + 1][xoff] = pack_dup(xr.y);
        *(ull*)&Xs[lq*4 + 2][xoff] = pack_dup(xr.z);
        *(ull*)&Xs[lq*4 + 3][xoff] = pack_dup(xr.w);

        // A: plain [k][o]
        As[lq*4 + 0][lr      ] = ar0.x;  As[lq*4 + 1][lr      ] = ar0.y;
        As[lq*4 + 2][lr      ] = ar0.z;  As[lq*4 + 3][lr      ] = ar0.w;
        As[lq*4 + 0][lr +  64] = ar1.x;  As[lq*4 + 1][lr +  64] = ar1.y;
        As[lq*4 + 2][lr +  64] = ar1.z;  As[lq*4 + 3][lr +  64] = ar1.w;
        As[lq*4 + 0][lr + 128] = ar2.x;  As[lq*4 + 1][lr + 128] = ar2.y;
        As[lq*4 + 2][lr + 128] = ar2.z;  As[lq*4 + 3][lr + 128] = ar2.w;
        As[lq*4 + 0][lr + 192] = ar3.x;  As[lq*4 + 1][lr + 192] = ar3.y;
        As[lq*4 + 2][lr + 192] = ar3.z;  As[lq*4 + 3][lr + 192] = ar3.w;

        __syncthreads();

        if (s + 1 < NSTAGE) {
            const int ks = (s + 1) * BK;
            xr  = *(const float4*)(xg + ks);
            ar0 = *(const float4*)(Ag + ks);
            ar1 = *(const float4*)(Ag +  64 * DIN + ks);
            ar2 = *(const float4*)(Ag + 128 * DIN + ks);
            ar3 = *(const float4*)(Ag + 192 * DIN + ks);
        }

        #pragma unroll
        for (int k = 0; k < BK; ++k) {
            // X: 4 LDS.128, each 8 consecutive chunks across mg -> 1 wf
            ull xp[8];
            #pragma unroll
            for (int h = 0; h < 4; ++h) {
                ulonglong2 v = *(const ulonglong2*)&Xs[k][(h*8 + mg) * 4];
                xp[2*h]     = v.x;   // pair (x_m, x_m), m = mg*8 + 2h
                xp[2*h + 1] = v.y;   // m = mg*8 + 2h + 1
            }
            // A: 2 LDS.128 natural pairs, 64B unique, broadcast over mg -> 1 wf each
            ulonglong2 a0 = *(const ulonglong2*)&As[k][oBase];
            ulonglong2 a1 = *(const ulonglong2*)&As[k][oBase + 4];
            ull ap[4] = {a0.x, a0.y, a1.x, a1.y};

            #pragma unroll
            for (int m = 0; m < 8; ++m) {
                ffma2(acc[m][0], xp[m], ap[0]);
                ffma2(acc[m][1], xp[m], ap[1]);
                ffma2(acc[m][2], xp[m], ap[2]);
                ffma2(acc[m][3], xp[m], ap[3]);
            }
        }
    }

    // epilogue: bias + store, 8 consecutive o per thread (2x float4)
    const float4 b0 = *(const float4*)(Bp + (size_t)n * DOUT + oBase);
    const float4 b1 = *(const float4*)(Bp + (size_t)n * DOUT + oBase + 4);

    #pragma unroll
    for (int m = 0; m < 8; ++m) {
        float2 v0 = unpack2(acc[m][0]);
        float2 v1 = unpack2(acc[m][1]);
        float2 v2 = unpack2(acc[m][2]);
        float2 v3 = unpack2(acc[m][3]);
        float4 o0 = make_float4(v0.x + b0.x, v0.y + b0.y, v1.x + b0.z, v1.y + b0.w);
        float4 o1 = make_float4(v2.x + b1.x, v2.y + b1.y, v3.x + b1.z, v3.y + b1.w);
        float* og_ptr = out + (size_t)(mBase + mg*8 + m) * (NSPL * DOUT)
                            + (size_t)n * DOUT + oBase;
        *(float4*)og_ptr       = o0;
        *(float4*)(og_ptr + 4) = o1;
    }
}

extern "C" void kernel_launch(void* const* d_in, const int* in_sizes, int n_in,
                              void* d_out, int out_size)
{
    const float* x  = (const float*)d_in[0];
    const float* A  = (const float*)d_in[1];
    const float* Bp = (const float*)d_in[2];
    float* out = (float*)d_out;

    dim3 grid(BSZ / BM, NSPL);   // (32, 256)
    multidense_kernel<<<grid, 256>>>(x, A, Bp, out);
}

// round 9
// speedup vs baseline: 2.5630x; 2.5630x over previous
#include <cuda_runtime.h>
#include <cstdint>

// MultiDense y[b,n,o] = sum_i x[b,n,i]*A[n,o,i] + Bp[n,o]
// bf16 split (hh + lh + hl) on legacy HMMA path (mma.sync m16n8k16), fp32 accum.
// Per CTA: one group n, 128 batch rows, all 256 outputs. K=256 staged by 64,
// raw fp32 double-buffered in smem via cp.async; fragments built in regs.

#define BSZ   2048
#define NSPL  256
#define DIN   256
#define DOUT  256
#define BM    128
#define KC    64
#define NSTG  4

#define XBYTES (BM*KC*4)        // 32768
#define ABYTES (DOUT*KC*4)      // 65536
#define STG_BYTES (XBYTES + ABYTES)
#define SMEM_TOTAL (2*STG_BYTES)   // 196608

__device__ __forceinline__ uint32_t s2u(const void* p){
    uint32_t a;
    asm("{ .reg .u64 t; cvta.to.shared.u64 t, %1; cvt.u32.u64 %0, t; }" : "=r"(a) : "l"(p));
    return a;
}
__device__ __forceinline__ void cpasync16(uint32_t s, const void* g){
    asm volatile("cp.async.cg.shared.global [%0], [%1], 16;" :: "r"(s), "l"(g));
}
__device__ __forceinline__ float2 lds2(uint32_t a){
    float2 r;
    asm volatile("ld.shared.v2.f32 {%0,%1}, [%2];" : "=f"(r.x), "=f"(r.y) : "r"(a));
    return r;
}
// fp32 pair -> bf16x2 hi (truncated) + bf16x2 lo (rounded residual)
__device__ __forceinline__ void cvt2(float2 v, uint32_t& hi, uint32_t& lo){
    uint32_t u0 = __float_as_uint(v.x), u1 = __float_as_uint(v.y);
    asm("prmt.b32 %0, %1, %2, 0x7632;" : "=r"(hi) : "r"(u0), "r"(u1));
    float l0 = v.x - __uint_as_float(u0 & 0xFFFF0000u);
    float l1 = v.y - __uint_as_float(u1 & 0xFFFF0000u);
    asm("cvt.rn.bf16x2.f32 %0, %1, %2;" : "=r"(lo) : "f"(l1), "f"(l0));
}
__device__ __forceinline__ void mma_bf16(float* c, const uint32_t* a, const uint32_t* b){
    asm volatile("mma.sync.aligned.m16n8k16.row.col.f32.bf16.bf16.f32 "
        "{%0,%1,%2,%3}, {%4,%5,%6,%7}, {%8,%9}, {%0,%1,%2,%3};"
        : "+f"(c[0]), "+f"(c[1]), "+f"(c[2]), "+f"(c[3])
        : "r"(a[0]), "r"(a[1]), "r"(a[2]), "r"(a[3]), "r"(b[0]), "r"(b[1]));
}

// swizzle: XOR 32B-chunk index (bits 5-6) with row&3; conflict-free per 16-lane phase
#define SWOFF(row, cb) ((uint32_t)((row)*256 + ((cb) ^ (((row)&3)<<5))))

__global__ __launch_bounds__(256, 1)
void multidense_mma(const float* __restrict__ x, const float* __restrict__ A,
                    const float* __restrict__ Bp, float* __restrict__ out)
{
    extern __shared__ char smem[];
    const uint32_t sb = s2u(smem);
    const int tid  = threadIdx.x;
    const int wid  = tid >> 5, lane = tid & 31;
    const int qr   = lane >> 2, qc = lane & 3;
    const int n    = blockIdx.y;
    const int mBase= blockIdx.x * BM;
    const int m0w  = (wid >> 2) * 64;      // warp m offset (0 or 64)
    const int n0w  = (wid & 3) * 64;       // warp n offset (0,64,128,192)

    const float* xs  = x + (size_t)mBase * (NSPL*DIN) + (size_t)n * DIN;
    const float* as_ = A + (size_t)n * (DOUT*DIN);

    float acc[4][8][4];
    #pragma unroll
    for (int mb = 0; mb < 4; ++mb)
        #pragma unroll
        for (int nb = 0; nb < 8; ++nb)
            #pragma unroll
            for (int e = 0; e < 4; ++e) acc[mb][nb][e] = 0.f;

    // ---- stage loader: 24 cp.async x 16B per thread ----
    auto load_stage = [&](int s){
        const uint32_t base = sb + (uint32_t)(s & 1) * STG_BYTES;
        const int ks0 = s * KC;
        #pragma unroll
        for (int j = 0; j < 8; ++j){                 // X: 128 x 64 fp32
            int g = tid + 256*j, row = g >> 4, c16 = g & 15;
            cpasync16(base + SWOFF(row, c16*16),
                      xs + (size_t)row*(NSPL*DIN) + ks0 + c16*4);
        }
        #pragma unroll
        for (int j = 0; j < 16; ++j){                // A: 256 x 64 fp32
            int g = tid + 256*j, row = g >> 4, c16 = g & 15;
            cpasync16(base + XBYTES + SWOFF(row, c16*16),
                      as_ + (size_t)row*DIN + ks0 + c16*4);
        }
        asm volatile("cp.async.commit_group;" ::: "memory");
    };

    load_stage(0);

    for (int s = 0; s < NSTG; ++s){
        if (s + 1 < NSTG){
            load_stage(s + 1);
            asm volatile("cp.async.wait_group 1;" ::: "memory");
        } else {
            asm volatile("cp.async.wait_group 0;" ::: "memory");
        }
        __syncthreads();

        const uint32_t xb = sb + (uint32_t)(s & 1) * STG_BYTES;
        const uint32_t ab = xb + XBYTES;

        #pragma unroll
        for (int kk = 0; kk < 4; ++kk){
            const int cb0 = kk*64 + qc*8;

            // B-operand frags (A matrix): 8 n8-blocks, hi+lo
            uint32_t ah[8][2], al[8][2];
            #pragma unroll
            for (int nb = 0; nb < 8; ++nb){
                int row = n0w + nb*8 + qr;
                cvt2(lds2(ab + SWOFF(row, cb0     )), ah[nb][0], al[nb][0]);
                cvt2(lds2(ab + SWOFF(row, cb0 + 32)), ah[nb][1], al[nb][1]);
            }

            #pragma unroll
            for (int mb = 0; mb < 4; ++mb){
                uint32_t xh[4], xl[4];
                int r0 = m0w + mb*16 + qr;
                int r1 = r0 + 8;
                cvt2(lds2(xb + SWOFF(r0, cb0     )), xh[0], xl[0]);
                cvt2(lds2(xb + SWOFF(r1, cb0     )), xh[1], xl[1]);
                cvt2(lds2(xb + SWOFF(r0, cb0 + 32)), xh[2], xl[2]);
                cvt2(lds2(xb + SWOFF(r1, cb0 + 32)), xh[3], xl[3]);

                #pragma unroll
                for (int nb = 0; nb < 8; ++nb){
                    mma_bf16(acc[mb][nb], xh, ah[nb]);   // hh
                    mma_bf16(acc[mb][nb], xl, ah[nb]);   // lh
                    mma_bf16(acc[mb][nb], xh, al[nb]);   // hl
                }
            }
        }
        __syncthreads();
    }

    // ---- epilogue: bias + direct STG.64 (32B sectors per lane-quad) ----
    #pragma unroll
    for (int nb = 0; nb < 8; ++nb){
        const int col = n0w + nb*8 + qc*2;
        const float2 bb = *(const float2*)(Bp + (size_t)n*DOUT + col);
        #pragma unroll
        for (int mb = 0; mb < 4; ++mb){
            const int rg0 = mBase + m0w + mb*16 + qr;
            float2 v0 = make_float2(acc[mb][nb][0] + bb.x, acc[mb][nb][1] + bb.y);
            float2 v1 = make_float2(acc[mb][nb][2] + bb.x, acc[mb][nb][3] + bb.y);
            *(float2*)(out + (size_t)rg0     *(NSPL*DOUT) + (size_t)n*DOUT + col) = v0;
            *(float2*)(out + (size_t)(rg0+8) *(NSPL*DOUT) + (size_t)n*DOUT + col) = v1;
        }
    }
}

extern "C" void kernel_launch(void* const* d_in, const int* in_sizes, int n_in,
                              void* d_out, int out_size)
{
    const float* x  = (const float*)d_in[0];
    const float* A  = (const float*)d_in[1];
    const float* Bp = (const float*)d_in[2];
    float* out = (float*)d_out;

    cudaFuncSetAttribute(multidense_mma, cudaFuncAttributeMaxDynamicSharedMemorySize, SMEM_TOTAL);
    dim3 grid(BSZ / BM, NSPL);   // (16, 256) = 4096 CTAs
    multidense_mma<<<grid, 256, SMEM_TOTAL>>>(x, A, Bp, out);
}

// round 10
// speedup vs baseline: 3.1821x; 1.2416x over previous
#include <cuda_runtime.h>
#include <cstdint>

// MultiDense y[b,n,o] = sum_i x[b,n,i]*A[n,o,i] + Bp[n,o]
// fp16 2-term split (x = xh+xl, A ~= ah): y = xh*ah + xl*ah, fp32 accum.
// Stages: cp.async fp32 -> convert pass -> ldmatrix + mma.m16n8k16.f16.
// Per CTA: one group n, 128 batch rows, 256 outputs. K=256 in 4 chunks of 64.

#define BSZ   2048
#define NSPL  256
#define DIN   256
#define DOUT  256
#define BM    128
#define KC    64
#define NSTG  4

#define XBYTES (BM*KC*4)          // 32768 fp32 X stage
#define ABYTES (DOUT*KC*4)        // 65536 fp32 A stage
#define STG_BYTES (XBYTES + ABYTES)   // 98304
#define XH_T  STG_BYTES           // fp16 tiles after fp32 stage
#define XL_T  (XH_T + BM*KC*2)    // +16384
#define AH_T  (XL_T + BM*KC*2)    // +16384
#define SMEM_TOTAL (AH_T + DOUT*KC*2)  // 163840 (160KB)

__device__ __forceinline__ uint32_t s2u(const void* p){
    uint32_t a;
    asm("{ .reg .u64 t; cvta.to.shared.u64 t, %1; cvt.u32.u64 %0, t; }" : "=r"(a) : "l"(p));
    return a;
}
__device__ __forceinline__ void cpasync16(uint32_t s, const void* g){
    asm volatile("cp.async.cg.shared.global [%0], [%1], 16;" :: "r"(s), "l"(g));
}
__device__ __forceinline__ float4 lds4(uint32_t a){
    float4 r;
    asm volatile("ld.shared.v4.f32 {%0,%1,%2,%3}, [%4];"
        : "=f"(r.x), "=f"(r.y), "=f"(r.z), "=f"(r.w) : "r"(a));
    return r;
}
__device__ __forceinline__ void sts64(uint32_t a, uint32_t v0, uint32_t v1){
    asm volatile("st.shared.v2.b32 [%0], {%1,%2};" :: "r"(a), "r"(v0), "r"(v1) : "memory");
}
// fp32 pair -> fp16x2 hi (rn) + fp16x2 lo (residual)
__device__ __forceinline__ void splitf16_2(float2 v, uint32_t& hi, uint32_t& lo){
    uint32_t h;
    asm("cvt.rn.f16x2.f32 %0, %1, %2;" : "=r"(h) : "f"(v.y), "f"(v.x));
    float f0, f1;
    asm("{ .reg .b16 a, b; mov.b32 {a, b}, %2; cvt.f32.f16 %0, a; cvt.f32.f16 %1, b; }"
        : "=f"(f0), "=f"(f1) : "r"(h));
    float l0 = v.x - f0, l1 = v.y - f1;
    asm("cvt.rn.f16x2.f32 %0, %1, %2;" : "=r"(lo) : "f"(l1), "f"(l0));
    hi = h;
}
__device__ __forceinline__ uint32_t cvtf16_2(float2 v){
    uint32_t h;
    asm("cvt.rn.f16x2.f32 %0, %1, %2;" : "=r"(h) : "f"(v.y), "f"(v.x));
    return h;
}
__device__ __forceinline__ void ldsm4(uint32_t a, uint32_t& r0, uint32_t& r1,
                                      uint32_t& r2, uint32_t& r3){
    asm volatile("ldmatrix.sync.aligned.m8n8.x4.shared.b16 {%0,%1,%2,%3}, [%4];"
        : "=r"(r0), "=r"(r1), "=r"(r2), "=r"(r3) : "r"(a));
}
__device__ __forceinline__ void mma_f16(float* c, const uint32_t* a, const uint32_t* b){
    asm volatile("mma.sync.aligned.m16n8k16.row.col.f32.f16.f16.f32 "
        "{%0,%1,%2,%3}, {%4,%5,%6,%7}, {%8,%9}, {%0,%1,%2,%3};"
        : "+f"(c[0]), "+f"(c[1]), "+f"(c[2]), "+f"(c[3])
        : "r"(a[0]), "r"(a[1]), "r"(a[2]), "r"(a[3]), "r"(b[0]), "r"(b[1]));
}

// fp32 stage swizzle (cp.async / convert reads), 32B-chunk XOR
#define SWOFF(row, cb) ((uint32_t)((row)*256 + ((cb) ^ (((row)&3)<<5))))
// fp16 tile: 128B/row, 16B chunk c (0-7) XOR row&7; q = 4-elem quad (0-15)
#define TQOFF(row, q)  ((uint32_t)((row)*128 + (((((q)>>1) ^ ((row)&7)))<<4) + ((q)&1)*8))

__global__ __launch_bounds__(256, 1)
void multidense_mma(const float* __restrict__ x, const float* __restrict__ A,
                    const float* __restrict__ Bp, float* __restrict__ out)
{
    extern __shared__ char smem[];
    const uint32_t sb = s2u(smem);
    const int tid  = threadIdx.x;
    const int wid  = tid >> 5, lane = tid & 31;
    const int qr   = lane >> 2, qc = lane & 3;
    const int t8   = lane >> 3, r8 = lane & 7;
    const int n    = blockIdx.y;
    const int mBase= blockIdx.x * BM;
    const int m0w  = (wid >> 2) * 64;
    const int n0w  = (wid & 3) * 64;

    const float* xs  = x + (size_t)mBase * (NSPL*DIN) + (size_t)n * DIN;
    const float* as_ = A + (size_t)n * (DOUT*DIN);

    float acc[4][8][4];
    #pragma unroll
    for (int mb = 0; mb < 4; ++mb)
        #pragma unroll
        for (int nb = 0; nb < 8; ++nb)
            #pragma unroll
            for (int e = 0; e < 4; ++e) acc[mb][nb][e] = 0.f;

    // ldmatrix per-lane address bases
    // X mats: (m0-7,klo)(m8-15,klo)(m0-7,khi)(m8-15,khi): mrow+=(t8&1)*8, kchunk+=(t8>>1)
    // A mats: (n0-7,klo)(n0-7,khi)(n8-15,klo)(n8-15,khi): nrow+=(t8>>1)*8, kchunk+=(t8&1)
    uint32_t xrb[4], xsw[4], arb[4], asw[4];
    const int kax = t8 >> 1, kaa = t8 & 1;
    #pragma unroll
    for (int mb = 0; mb < 4; ++mb){
        int row = m0w + mb*16 + (t8 & 1)*8 + r8;
        xrb[mb] = sb + XH_T + (uint32_t)row*128; xsw[mb] = row & 7;
    }
    #pragma unroll
    for (int p = 0; p < 4; ++p){
        int row = n0w + p*16 + (t8 >> 1)*8 + r8;
        arb[p] = sb + AH_T + (uint32_t)row*128; asw[p] = row & 7;
    }

    auto load_stage = [&](int s){
        const int ks0 = s * KC;
        #pragma unroll
        for (int j = 0; j < 8; ++j){                 // X: 128 x 64 fp32
            int g = tid + 256*j, row = g >> 4, c16 = g & 15;
            cpasync16(sb + SWOFF(row, c16*16),
                      xs + (size_t)row*(NSPL*DIN) + ks0 + c16*4);
        }
        #pragma unroll
        for (int j = 0; j < 16; ++j){                // A: 256 x 64 fp32
            int g = tid + 256*j, row = g >> 4, c16 = g & 15;
            cpasync16(sb + XBYTES + SWOFF(row, c16*16),
                      as_ + (size_t)row*DIN + ks0 + c16*4);
        }
        asm volatile("cp.async.commit_group;" ::: "memory");
    };

    load_stage(0);

    for (int s = 0; s < NSTG; ++s){
        asm volatile("cp.async.wait_group 0;" ::: "memory");
        __syncthreads();

        // ---- convert pass: fp32 stage -> fp16 tiles ----
        #pragma unroll
        for (int j = 0; j < 8; ++j){                 // X -> Xh, Xl
            int g = tid + 256*j, row = g >> 4, q = g & 15;
            float4 v = lds4(sb + SWOFF(row, q*16));
            uint32_t h0, l0, h1, l1;
            splitf16_2(make_float2(v.x, v.y), h0, l0);
            splitf16_2(make_float2(v.z, v.w), h1, l1);
            uint32_t off = TQOFF(row, q);
            sts64(sb + XH_T + off, h0, h1);
            sts64(sb + XL_T + off, l0, l1);
        }
        #pragma unroll
        for (int j = 0; j < 16; ++j){                // A -> Ah
            int g = tid + 256*j, row = g >> 4, q = g & 15;
            float4 v = lds4(sb + XBYTES + SWOFF(row, q*16));
            sts64(sb + AH_T + TQOFF(row, q),
                  cvtf16_2(make_float2(v.x, v.y)), cvtf16_2(make_float2(v.z, v.w)));
        }
        __syncthreads();                              // fp32 buf free, tiles ready

        if (s + 1 < NSTG) load_stage(s + 1);          // overlaps with compute

        // ---- mainloop: 4 x k16 slices ----
        #pragma unroll
        for (int kk = 0; kk < 4; ++kk){
            const int ck = kk*2;
            uint32_t ah[8][2];
            #pragma unroll
            for (int p = 0; p < 4; ++p){
                uint32_t addr = arb[p] + (uint32_t)(((ck + kaa) ^ asw[p]) << 4);
                ldsm4(addr, ah[2*p][0], ah[2*p][1], ah[2*p+1][0], ah[2*p+1][1]);
            }
            #pragma unroll
            for (int mb = 0; mb < 4; ++mb){
                uint32_t xh[4], xl[4];
                uint32_t addr = xrb[mb] + (uint32_t)(((ck + kax) ^ xsw[mb]) << 4);
                ldsm4(addr,         xh[0], xh[1], xh[2], xh[3]);
                ldsm4(addr + 16384, xl[0], xl[1], xl[2], xl[3]);   // XL tile
                #pragma unroll
                for (int nb = 0; nb < 8; ++nb){
                    mma_f16(acc[mb][nb], xh, ah[nb]);   // xh * ah
                    mma_f16(acc[mb][nb], xl, ah[nb]);   // xl * ah
                }
            }
        }
        __syncthreads();                              // tiles free for next convert
    }

    // ---- epilogue: bias + STG.64 ----
    #pragma unroll
    for (int nb = 0; nb < 8; ++nb){
        const int col = n0w + nb*8 + qc*2;
        const float2 bb = *(const float2*)(Bp + (size_t)n*DOUT + col);
        #pragma unroll
        for (int mb = 0; mb < 4; ++mb){
            const int rg0 = mBase + m0w + mb*16 + qr;
            float2 v0 = make_float2(acc[mb][nb][0] + bb.x, acc[mb][nb][1] + bb.y);
            float2 v1 = make_float2(acc[mb][nb][2] + bb.x, acc[mb][nb][3] + bb.y);
            *(float2*)(out + (size_t)rg0     *(NSPL*DOUT) + (size_t)n*DOUT + col) = v0;
            *(float2*)(out + (size_t)(rg0+8) *(NSPL*DOUT) + (size_t)n*DOUT + col) = v1;
        }
    }
}

extern "C" void kernel_launch(void* const* d_in, const int* in_sizes, int n_in,
                              void* d_out, int out_size)
{
    const float* x  = (const float*)d_in[0];
    const float* A  = (const float*)d_in[1];
    const float* Bp = (const float*)d_in[2];
    float* out = (float*)d_out;

    cudaFuncSetAttribute(multidense_mma, cudaFuncAttributeMaxDynamicSharedMemorySize, SMEM_TOTAL);
    dim3 grid(BSZ / BM, NSPL);   // (16, 256) = 4096 CTAs
    multidense_mma<<<grid, 256, SMEM_TOTAL>>>(x, A, Bp, out);
}

// round 11
// speedup vs baseline: 3.5467x; 1.1146x over previous
#include <cuda_runtime.h>
#include <cstdint>

// MultiDense y[b,n,o] = sum_i x[b,n,i]*A[n,o,i] + Bp[n,o]
// fp16 2-term split (x = xh+xl, A ~= ah), fp32 accum on mma.m16n8k16.
// R11: A pre-converted to fp16 by a pre-pass kernel (redundant per-CTA A
// conversion removed); everything double-buffered; only X convert in-CTA.

#define BSZ   2048
#define NSPL  256
#define DIN   256
#define DOUT  256
#define BM    128
#define KC    64
#define NSTG  4

// smem layout (bytes): all double-buffered
#define XF0   0        // X fp32 stage: 2 x 32768
#define XH0   65536    // Xh fp16 tile: 2 x 16384
#define XL0   98304    // Xl fp16 tile: 2 x 16384   (XL = XH + 32768)
#define AH0   131072   // Ah fp16 tile: 2 x 32768
#define SMEM_TOTAL 196608

// fp16 A scratch, written by pre-pass each launch (device-global: allowed)
__device__ uint32_t Ah_g[(size_t)NSPL * DOUT * DIN / 2];   // 32 MB

__device__ __forceinline__ uint32_t s2u(const void* p){
    uint32_t a;
    asm("{ .reg .u64 t; cvta.to.shared.u64 t, %1; cvt.u32.u64 %0, t; }" : "=r"(a) : "l"(p));
    return a;
}
__device__ __forceinline__ void cpasync16(uint32_t s, const void* g){
    asm volatile("cp.async.cg.shared.global [%0], [%1], 16;" :: "r"(s), "l"(g));
}
__device__ __forceinline__ float4 lds4(uint32_t a){
    float4 r;
    asm volatile("ld.shared.v4.f32 {%0,%1,%2,%3}, [%4];"
        : "=f"(r.x), "=f"(r.y), "=f"(r.z), "=f"(r.w) : "r"(a));
    return r;
}
__device__ __forceinline__ void sts64(uint32_t a, uint32_t v0, uint32_t v1){
    asm volatile("st.shared.v2.b32 [%0], {%1,%2};" :: "r"(a), "r"(v0), "r"(v1) : "memory");
}
__device__ __forceinline__ uint32_t cvtf16_2(float2 v){
    uint32_t h;
    asm("cvt.rn.f16x2.f32 %0, %1, %2;" : "=r"(h) : "f"(v.y), "f"(v.x));
    return h;
}
// fp32 pair -> fp16x2 hi (rn) + fp16x2 lo (residual)
__device__ __forceinline__ void splitf16_2(float2 v, uint32_t& hi, uint32_t& lo){
    uint32_t h = cvtf16_2(v);
    float f0, f1;
    asm("{ .reg .b16 a, b; mov.b32 {a, b}, %2; cvt.f32.f16 %0, a; cvt.f32.f16 %1, b; }"
        : "=f"(f0), "=f"(f1) : "r"(h));
    float l0 = v.x - f0, l1 = v.y - f1;
    asm("cvt.rn.f16x2.f32 %0, %1, %2;" : "=r"(lo) : "f"(l1), "f"(l0));
    hi = h;
}
__device__ __forceinline__ void ldsm4(uint32_t a, uint32_t& r0, uint32_t& r1,
                                      uint32_t& r2, uint32_t& r3){
    asm volatile("ldmatrix.sync.aligned.m8n8.x4.shared.b16 {%0,%1,%2,%3}, [%4];"
        : "=r"(r0), "=r"(r1), "=r"(r2), "=r"(r3) : "r"(a));
}
__device__ __forceinline__ void mma_f16(float* c, const uint32_t* a, const uint32_t* b){
    asm volatile("mma.sync.aligned.m16n8k16.row.col.f32.f16.f16.f32 "
        "{%0,%1,%2,%3}, {%4,%5,%6,%7}, {%8,%9}, {%0,%1,%2,%3};"
        : "+f"(c[0]), "+f"(c[1]), "+f"(c[2]), "+f"(c[3])
        : "r"(a[0]), "r"(a[1]), "r"(a[2]), "r"(a[3]), "r"(b[0]), "r"(b[1]));
}

// fp32 stage swizzle (256B rows), 32B-chunk XOR
#define SWOFF(row, cb) ((uint32_t)((row)*256 + ((cb) ^ (((row)&3)<<5))))
// fp16 tile (128B rows): 16B chunk c (0-7) XOR (row&7); q = 4-elem quad (0-15)
#define TQOFF(row, q)  ((uint32_t)((row)*128 + (((((q)>>1) ^ ((row)&7)))<<4) + ((q)&1)*8))

// ---- pre-pass: A fp32 -> fp16 scratch (each thread: 8 floats -> uint4) ----
__global__ __launch_bounds__(256, 8)
void convertA_kernel(const float* __restrict__ A){
    size_t i = (size_t)blockIdx.x * 256 + threadIdx.x;     // 2,097,152 threads
    const float4* s = (const float4*)A + 2*i;
    float4 v0 = s[0], v1 = s[1];
    uint4 o;
    o.x = cvtf16_2(make_float2(v0.x, v0.y));
    o.y = cvtf16_2(make_float2(v0.z, v0.w));
    o.z = cvtf16_2(make_float2(v1.x, v1.y));
    o.w = cvtf16_2(make_float2(v1.z, v1.w));
    ((uint4*)Ah_g)[i] = o;
}

__global__ __launch_bounds__(256, 1)
void multidense_mma(const float* __restrict__ x,
                    const float* __restrict__ Bp, float* __restrict__ out)
{
    extern __shared__ char smem[];
    const uint32_t sb = s2u(smem);
    const int tid  = threadIdx.x;
    const int wid  = tid >> 5, lane = tid & 31;
    const int qr   = lane >> 2, qc = lane & 3;
    const int t8   = lane >> 3, r8 = lane & 7;
    const int n    = blockIdx.y;
    const int mBase= blockIdx.x * BM;
    const int m0w  = (wid >> 2) * 64;
    const int n0w  = (wid & 3) * 64;

    const float* xs = x + (size_t)mBase * (NSPL*DIN) + (size_t)n * DIN;
    const char*  ag = (const char*)Ah_g + (size_t)n * (DOUT*DIN) * 2;

    float acc[4][8][4];
    #pragma unroll
    for (int mb = 0; mb < 4; ++mb)
        #pragma unroll
        for (int nb = 0; nb < 8; ++nb)
            #pragma unroll
            for (int e = 0; e < 4; ++e) acc[mb][nb][e] = 0.f;

    // ldmatrix per-lane bases (buffer offset added per stage)
    uint32_t xrb[4], xsw[4], arb[4], asw[4];
    const int kax = t8 >> 1, kaa = t8 & 1;
    #pragma unroll
    for (int mb = 0; mb < 4; ++mb){
        int row = m0w + mb*16 + (t8 & 1)*8 + r8;
        xrb[mb] = sb + XH0 + (uint32_t)row*128; xsw[mb] = row & 7;
    }
    #pragma unroll
    for (int p = 0; p < 4; ++p){
        int row = n0w + p*16 + (t8 >> 1)*8 + r8;
        arb[p] = sb + AH0 + (uint32_t)row*128; asw[p] = row & 7;
    }

    auto load_stage = [&](int s){
        const int b = s & 1;
        const int ks0 = s * KC;
        const uint32_t xfb = sb + XF0 + (uint32_t)b*32768;
        const uint32_t ahb = sb + AH0 + (uint32_t)b*32768;
        #pragma unroll
        for (int j = 0; j < 8; ++j){                 // X: 128 x 64 fp32
            int g = tid + 256*j, row = g >> 4, c16 = g & 15;
            cpasync16(xfb + SWOFF(row, c16*16),
                      xs + (size_t)row*(NSPL*DIN) + ks0 + c16*4);
        }
        #pragma unroll
        for (int j = 0; j < 8; ++j){                 // Ah fp16: 256 rows x 64 k
            int g = tid + 256*j, row = g >> 3, c = g & 7;
            cpasync16(ahb + (uint32_t)row*128 + (uint32_t)((c ^ (row & 7)) << 4),
                      ag + ((size_t)row*DIN + ks0 + c*8)*2);
        }
        asm volatile("cp.async.commit_group;" ::: "memory");
    };

    load_stage(0);

    for (int s = 0; s < NSTG; ++s){
        const int b = s & 1;
        asm volatile("cp.async.wait_group 0;" ::: "memory");   // stage s arrived
        __syncthreads();   // publish loads; all warps done with buffers (s+1)&1

        if (s + 1 < NSTG) load_stage(s + 1);                   // overlaps below

        // ---- convert X(s): fp32 -> Xh/Xl tiles ----
        {
            const uint32_t xfb = sb + XF0 + (uint32_t)b*32768;
            const uint32_t xhb = sb + XH0 + (uint32_t)b*16384;
            #pragma unroll
            for (int j = 0; j < 8; ++j){
                int g = tid + 256*j, row = g >> 4, q = g & 15;
                float4 v = lds4(xfb + SWOFF(row, q*16));
                uint32_t h0, l0, h1, l1;
                splitf16_2(make_float2(v.x, v.y), h0, l0);
                splitf16_2(make_float2(v.z, v.w), h1, l1);
                uint32_t off = TQOFF(row, q);
                sts64(xhb + off,         h0, h1);
                sts64(xhb + off + 32768, l0, l1);    // XL = XH + 32768
            }
        }
        __syncthreads();   // tiles ready

        // ---- mainloop: 4 x k16 slices, pure LDSM + HMMA ----
        const uint32_t xo = (uint32_t)b*16384, ao = (uint32_t)b*32768;
        #pragma unroll
        for (int kk = 0; kk < 4; ++kk){
            const int ck = kk*2;
            uint32_t ah[8][2];
            #pragma unroll
            for (int p = 0; p < 4; ++p){
                uint32_t addr = arb[p] + ao + (uint32_t)(((ck + kaa) ^ asw[p]) << 4);
                ldsm4(addr, ah[2*p][0], ah[2*p][1], ah[2*p+1][0], ah[2*p+1][1]);
            }
            #pragma unroll
            for (int mb = 0; mb < 4; ++mb){
                uint32_t xh[4], xl[4];
                uint32_t addr = xrb[mb] + xo + (uint32_t)(((ck + kax) ^ xsw[mb]) << 4);
                ldsm4(addr,         xh[0], xh[1], xh[2], xh[3]);
                ldsm4(addr + 32768, xl[0], xl[1], xl[2], xl[3]);
                #pragma unroll
                for (int nb = 0; nb < 8; ++nb){
                    mma_f16(acc[mb][nb], xh, ah[nb]);
                    mma_f16(acc[mb][nb], xl, ah[nb]);
                }
            }
        }
    }

    // ---- epilogue: bias + STG.64 ----
    #pragma unroll
    for (int nb = 0; nb < 8; ++nb){
        const int col = n0w + nb*8 + qc*2;
        const float2 bb = *(const float2*)(Bp + (size_t)n*DOUT + col);
        #pragma unroll
        for (int mb = 0; mb < 4; ++mb){
            const int rg0 = mBase + m0w + mb*16 + qr;
            float2 v0 = make_float2(acc[mb][nb][0] + bb.x, acc[mb][nb][1] + bb.y);
            float2 v1 = make_float2(acc[mb][nb][2] + bb.x, acc[mb][nb][3] + bb.y);
            *(float2*)(out + (size_t)rg0     *(NSPL*DOUT) + (size_t)n*DOUT + col) = v0;
            *(float2*)(out + (size_t)(rg0+8) *(NSPL*DOUT) + (size_t)n*DOUT + col) = v1;
        }
    }
}

extern "C" void kernel_launch(void* const* d_in, const int* in_sizes, int n_in,
                              void* d_out, int out_size)
{
    const float* x  = (const float*)d_in[0];
    const float* A  = (const float*)d_in[1];
    const float* Bp = (const float*)d_in[2];
    float* out = (float*)d_out;

    // pre-pass: A -> fp16 scratch (16.77M elems / 8 per thread)
    convertA_kernel<<<8192, 256>>>(A);

    cudaFuncSetAttribute(multidense_mma, cudaFuncAttributeMaxDynamicSharedMemorySize, SMEM_TOTAL);
    dim3 grid(BSZ / BM, NSPL);   // (16, 256) = 4096 CTAs
    multidense_mma<<<grid, 256, SMEM_TOTAL>>>(x, Bp, out);
}

// round 12
// speedup vs baseline: 3.8278x; 1.0793x over previous
#include <cuda_runtime.h>
#include <cstdint>

// MultiDense y[b,n,o] = sum_i x[b,n,i]*A[n,o,i] + Bp[n,o]
// fp16 2-term split (x = xh+xl, A ~= ah), fp32 accum on mma.m16n8k16.
// R12: 2 CTAs/SM (BM=64, 64 acc regs, 112KB smem) so convert/load/barrier
// holes of one CTA overlap the other's HMMA stream.

#define BSZ   2048
#define NSPL  256
#define DIN   256
#define DOUT  256
#define BM    64
#define KC    64
#define NSTG  4

// smem layout (bytes), per CTA = 112 KB
#define XF0   0        // X fp32 stage, single: 16384
#define XH0   16384    // Xh fp16: 2 x 8192
#define XL0   32768    // Xl fp16: 2 x 8192   (XL = XH + 16384)
#define AH0   49152    // Ah fp16: 2 x 32768
#define SMEM_TOTAL 114688

// fp16 A scratch, written by pre-pass each launch
__device__ uint32_t Ah_g[(size_t)NSPL * DOUT * DIN / 2];   // 32 MB

__device__ __forceinline__ uint32_t s2u(const void* p){
    uint32_t a;
    asm("{ .reg .u64 t; cvta.to.shared.u64 t, %1; cvt.u32.u64 %0, t; }" : "=r"(a) : "l"(p));
    return a;
}
__device__ __forceinline__ void cpasync16(uint32_t s, const void* g){
    asm volatile("cp.async.cg.shared.global [%0], [%1], 16;" :: "r"(s), "l"(g));
}
__device__ __forceinline__ float4 lds4(uint32_t a){
    float4 r;
    asm volatile("ld.shared.v4.f32 {%0,%1,%2,%3}, [%4];"
        : "=f"(r.x), "=f"(r.y), "=f"(r.z), "=f"(r.w) : "r"(a));
    return r;
}
__device__ __forceinline__ void sts64(uint32_t a, uint32_t v0, uint32_t v1){
    asm volatile("st.shared.v2.b32 [%0], {%1,%2};" :: "r"(a), "r"(v0), "r"(v1) : "memory");
}
__device__ __forceinline__ uint32_t cvtf16_2(float2 v){
    uint32_t h;
    asm("cvt.rn.f16x2.f32 %0, %1, %2;" : "=r"(h) : "f"(v.y), "f"(v.x));
    return h;
}
__device__ __forceinline__ void splitf16_2(float2 v, uint32_t& hi, uint32_t& lo){
    uint32_t h = cvtf16_2(v);
    float f0, f1;
    asm("{ .reg .b16 a, b; mov.b32 {a, b}, %2; cvt.f32.f16 %0, a; cvt.f32.f16 %1, b; }"
        : "=f"(f0), "=f"(f1) : "r"(h));
    float l0 = v.x - f0, l1 = v.y - f1;
    asm("cvt.rn.f16x2.f32 %0, %1, %2;" : "=r"(lo) : "f"(l1), "f"(l0));
    hi = h;
}
__device__ __forceinline__ void ldsm4(uint32_t a, uint32_t& r0, uint32_t& r1,
                                      uint32_t& r2, uint32_t& r3){
    asm volatile("ldmatrix.sync.aligned.m8n8.x4.shared.b16 {%0,%1,%2,%3}, [%4];"
        : "=r"(r0), "=r"(r1), "=r"(r2), "=r"(r3) : "r"(a));
}
__device__ __forceinline__ void mma_f16(float* c, const uint32_t* a, const uint32_t* b){
    asm volatile("mma.sync.aligned.m16n8k16.row.col.f32.f16.f16.f32 "
        "{%0,%1,%2,%3}, {%4,%5,%6,%7}, {%8,%9}, {%0,%1,%2,%3};"
        : "+f"(c[0]), "+f"(c[1]), "+f"(c[2]), "+f"(c[3])
        : "r"(a[0]), "r"(a[1]), "r"(a[2]), "r"(a[3]), "r"(b[0]), "r"(b[1]));
}

// fp32 stage swizzle (256B rows), 32B-chunk XOR
#define SWOFF(row, cb) ((uint32_t)((row)*256 + ((cb) ^ (((row)&3)<<5))))
// fp16 tile (128B rows): 16B chunk c (0-7) XOR (row&7); q = 4-elem quad (0-15)
#define TQOFF(row, q)  ((uint32_t)((row)*128 + (((((q)>>1) ^ ((row)&7)))<<4) + ((q)&1)*8))

// ---- pre-pass: A fp32 -> fp16 scratch ----
__global__ __launch_bounds__(256, 8)
void convertA_kernel(const float* __restrict__ A){
    size_t i = (size_t)blockIdx.x * 256 + threadIdx.x;
    const float4* s = (const float4*)A + 2*i;
    float4 v0 = s[0], v1 = s[1];
    uint4 o;
    o.x = cvtf16_2(make_float2(v0.x, v0.y));
    o.y = cvtf16_2(make_float2(v0.z, v0.w));
    o.z = cvtf16_2(make_float2(v1.x, v1.y));
    o.w = cvtf16_2(make_float2(v1.z, v1.w));
    ((uint4*)Ah_g)[i] = o;
}

__global__ __launch_bounds__(256, 2)
void multidense_mma(const float* __restrict__ x,
                    const float* __restrict__ Bp, float* __restrict__ out)
{
    extern __shared__ char smem[];
    const uint32_t sb = s2u(smem);
    const int tid  = threadIdx.x;
    const int wid  = tid >> 5, lane = tid & 31;
    const int qr   = lane >> 2, qc = lane & 3;
    const int t8   = lane >> 3, r8 = lane & 7;
    const int n    = blockIdx.y;
    const int mBase= blockIdx.x * BM;
    const int m0w  = (wid >> 2) * 32;      // warp m offset (0 or 32)
    const int n0w  = (wid & 3) * 64;       // warp n offset

    const float* xs = x + (size_t)mBase * (NSPL*DIN) + (size_t)n * DIN;
    const char*  ag = (const char*)Ah_g + (size_t)n * (DOUT*DIN) * 2;

    float acc[2][8][4];
    #pragma unroll
    for (int mb = 0; mb < 2; ++mb)
        #pragma unroll
        for (int nb = 0; nb < 8; ++nb)
            #pragma unroll
            for (int e = 0; e < 4; ++e) acc[mb][nb][e] = 0.f;

    // ldmatrix per-lane bases
    uint32_t xrb[2], xsw[2], arb[4], asw[4];
    const int kax = t8 >> 1, kaa = t8 & 1;
    #pragma unroll
    for (int mb = 0; mb < 2; ++mb){
        int row = m0w + mb*16 + (t8 & 1)*8 + r8;
        xrb[mb] = sb + XH0 + (uint32_t)row*128; xsw[mb] = row & 7;
    }
    #pragma unroll
    for (int p = 0; p < 4; ++p){
        int row = n0w + p*16 + (t8 >> 1)*8 + r8;
        arb[p] = sb + AH0 + (uint32_t)row*128; asw[p] = row & 7;
    }

    auto load_stage = [&](int s){
        const int b = s & 1;
        const int ks0 = s * KC;
        const uint32_t ahb = sb + AH0 + (uint32_t)b*32768;
        #pragma unroll
        for (int j = 0; j < 4; ++j){                 // X: 64 x 64 fp32 -> XF
            int g = tid + 256*j, row = g >> 4, c16 = g & 15;
            cpasync16(sb + XF0 + SWOFF(row, c16*16),
                      xs + (size_t)row*(NSPL*DIN) + ks0 + c16*4);
        }
        #pragma unroll
        for (int j = 0; j < 8; ++j){                 // Ah fp16: 256 rows x 64 k
            int g = tid + 256*j, row = g >> 3, c = g & 7;
            cpasync16(ahb + (uint32_t)row*128 + (uint32_t)((c ^ (row & 7)) << 4),
                      ag + ((size_t)row*DIN + ks0 + c*8)*2);
        }
        asm volatile("cp.async.commit_group;" ::: "memory");
    };

    load_stage(0);

    for (int s = 0; s < NSTG; ++s){
        const int b = s & 1;
        asm volatile("cp.async.wait_group 0;" ::: "memory");
        __syncthreads();   // stage s data visible to all warps

        // ---- convert X(s): XF -> Xh/Xl[b] ----
        {
            const uint32_t xhb = sb + XH0 + (uint32_t)b*8192;
            #pragma unroll
            for (int j = 0; j < 4; ++j){
                int g = tid + 256*j, row = g >> 4, q = g & 15;
                float4 v = lds4(sb + XF0 + SWOFF(row, q*16));
                uint32_t h0, l0, h1, l1;
                splitf16_2(make_float2(v.x, v.y), h0, l0);
                splitf16_2(make_float2(v.z, v.w), h1, l1);
                uint32_t off = TQOFF(row, q);
                sts64(xhb + off,         h0, h1);
                sts64(xhb + off + 16384, l0, l1);    // XL = XH + 16384
            }
        }
        __syncthreads();   // tiles ready; XF free for next load

        if (s + 1 < NSTG) load_stage(s + 1);   // overlaps mainloop below

        // ---- mainloop: 4 x k16 slices, pure LDSM + HMMA ----
        const uint32_t xo = (uint32_t)b*8192, ao = (uint32_t)b*32768;
        #pragma unroll
        for (int kk = 0; kk < 4; ++kk){
            const int ck = kk*2;
            uint32_t ah[8][2];
            #pragma unroll
            for (int p = 0; p < 4; ++p){
                uint32_t addr = arb[p] + ao + (uint32_t)(((ck + kaa) ^ asw[p]) << 4);
                ldsm4(addr, ah[2*p][0], ah[2*p][1], ah[2*p+1][0], ah[2*p+1][1]);
            }
            #pragma unroll
            for (int mb = 0; mb < 2; ++mb){
                uint32_t xh[4], xl[4];
                uint32_t addr = xrb[mb] + xo + (uint32_t)(((ck + kax) ^ xsw[mb]) << 4);
                ldsm4(addr,         xh[0], xh[1], xh[2], xh[3]);
                ldsm4(addr + 16384, xl[0], xl[1], xl[2], xl[3]);
                #pragma unroll
                for (int nb = 0; nb < 8; ++nb){
                    mma_f16(acc[mb][nb], xh, ah[nb]);
                    mma_f16(acc[mb][nb], xl, ah[nb]);
                }
            }
        }
    }

    // ---- epilogue: bias + STG.64 ----
    #pragma unroll
    for (int nb = 0; nb < 8; ++nb){
        const int col = n0w + nb*8 + qc*2;
        const float2 bb = *(const float2*)(Bp + (size_t)n*DOUT + col);
        #pragma unroll
        for (int mb = 0; mb < 2; ++mb){
            const int rg0 = mBase + m0w + mb*16 + qr;
            float2 v0 = make_float2(acc[mb][nb][0] + bb.x, acc[mb][nb][1] + bb.y);
            float2 v1 = make_float2(acc[mb][nb][2] + bb.x, acc[mb][nb][3] + bb.y);
            *(float2*)(out + (size_t)rg0     *(NSPL*DOUT) + (size_t)n*DOUT + col) = v0;
            *(float2*)(out + (size_t)(rg0+8) *(NSPL*DOUT) + (size_t)n*DOUT + col) = v1;
        }
    }
}

extern "C" void kernel_launch(void* const* d_in, const int* in_sizes, int n_in,
                              void* d_out, int out_size)
{
    const float* x  = (const float*)d_in[0];
    const float* A  = (const float*)d_in[1];
    const float* Bp = (const float*)d_in[2];
    float* out = (float*)d_out;

    convertA_kernel<<<8192, 256>>>(A);

    cudaFuncSetAttribute(multidense_mma, cudaFuncAttributeMaxDynamicSharedMemorySize, SMEM_TOTAL);
    dim3 grid(BSZ / BM, NSPL);   // (32, 256) = 8192 CTAs
    multidense_mma<<<grid, 256, SMEM_TOTAL>>>(x, Bp, out);
}

// round 13
// speedup vs baseline: 5.3061x; 1.3862x over previous
#include <cuda_runtime.h>
#include <cstdint>

// MultiDense y[b,n,o] = sum_i x[b,n,i]*A[n,o,i] + Bp[n,o]
// R13: pure fp16 GEMM (x ~= xh, A ~= ah), fp32 accum on mma.m16n8k16.
// Error budget: A-rounding 2.07e-4 (measured R12) + x-rounding ~2e-4 -> ~3e-4 < 1e-3.
// 2 CTAs/SM (BM=64, 96KB smem); A pre-converted fp16 once per launch.

#define BSZ   2048
#define NSPL  256
#define DIN   256
#define DOUT  256
#define BM    64
#define KC    64
#define NSTG  4

// smem layout (bytes), per CTA = 96 KB
#define XF0   0        // X fp32 stage, single: 16384
#define XH0   16384    // Xh fp16: 2 x 8192
#define AH0   32768    // Ah fp16: 2 x 32768
#define SMEM_TOTAL 98304

// fp16 A scratch, written by pre-pass each launch
__device__ uint32_t Ah_g[(size_t)NSPL * DOUT * DIN / 2];   // 32 MB

__device__ __forceinline__ uint32_t s2u(const void* p){
    uint32_t a;
    asm("{ .reg .u64 t; cvta.to.shared.u64 t, %1; cvt.u32.u64 %0, t; }" : "=r"(a) : "l"(p));
    return a;
}
__device__ __forceinline__ void cpasync16(uint32_t s, const void* g){
    asm volatile("cp.async.cg.shared.global [%0], [%1], 16;" :: "r"(s), "l"(g));
}
__device__ __forceinline__ float4 lds4(uint32_t a){
    float4 r;
    asm volatile("ld.shared.v4.f32 {%0,%1,%2,%3}, [%4];"
        : "=f"(r.x), "=f"(r.y), "=f"(r.z), "=f"(r.w) : "r"(a));
    return r;
}
__device__ __forceinline__ void sts64(uint32_t a, uint32_t v0, uint32_t v1){
    asm volatile("st.shared.v2.b32 [%0], {%1,%2};" :: "r"(a), "r"(v0), "r"(v1) : "memory");
}
__device__ __forceinline__ uint32_t cvtf16_2(float2 v){
    uint32_t h;
    asm("cvt.rn.f16x2.f32 %0, %1, %2;" : "=r"(h) : "f"(v.y), "f"(v.x));
    return h;
}
__device__ __forceinline__ void ldsm4(uint32_t a, uint32_t& r0, uint32_t& r1,
                                      uint32_t& r2, uint32_t& r3){
    asm volatile("ldmatrix.sync.aligned.m8n8.x4.shared.b16 {%0,%1,%2,%3}, [%4];"
        : "=r"(r0), "=r"(r1), "=r"(r2), "=r"(r3) : "r"(a));
}
__device__ __forceinline__ void mma_f16(float* c, const uint32_t* a, const uint32_t* b){
    asm volatile("mma.sync.aligned.m16n8k16.row.col.f32.f16.f16.f32 "
        "{%0,%1,%2,%3}, {%4,%5,%6,%7}, {%8,%9}, {%0,%1,%2,%3};"
        : "+f"(c[0]), "+f"(c[1]), "+f"(c[2]), "+f"(c[3])
        : "r"(a[0]), "r"(a[1]), "r"(a[2]), "r"(a[3]), "r"(b[0]), "r"(b[1]));
}

// fp32 stage swizzle (256B rows), 32B-chunk XOR
#define SWOFF(row, cb) ((uint32_t)((row)*256 + ((cb) ^ (((row)&3)<<5))))
// fp16 tile (128B rows): 16B chunk c (0-7) XOR (row&7); q = 4-elem quad (0-15)
#define TQOFF(row, q)  ((uint32_t)((row)*128 + (((((q)>>1) ^ ((row)&7)))<<4) + ((q)&1)*8))

// ---- pre-pass: A fp32 -> fp16 scratch ----
__global__ __launch_bounds__(256, 8)
void convertA_kernel(const float* __restrict__ A){
    size_t i = (size_t)blockIdx.x * 256 + threadIdx.x;
    const float4* s = (const float4*)A + 2*i;
    float4 v0 = s[0], v1 = s[1];
    uint4 o;
    o.x = cvtf16_2(make_float2(v0.x, v0.y));
    o.y = cvtf16_2(make_float2(v0.z, v0.w));
    o.z = cvtf16_2(make_float2(v1.x, v1.y));
    o.w = cvtf16_2(make_float2(v1.z, v1.w));
    ((uint4*)Ah_g)[i] = o;
}

__global__ __launch_bounds__(256, 2)
void multidense_mma(const float* __restrict__ x,
                    const float* __restrict__ Bp, float* __restrict__ out)
{
    extern __shared__ char smem[];
    const uint32_t sb = s2u(smem);
    const int tid  = threadIdx.x;
    const int wid  = tid >> 5, lane = tid & 31;
    const int qr   = lane >> 2, qc = lane & 3;
    const int t8   = lane >> 3, r8 = lane & 7;
    const int n    = blockIdx.y;
    const int mBase= blockIdx.x * BM;
    const int m0w  = (wid >> 2) * 32;      // warp m offset (0 or 32)
    const int n0w  = (wid & 3) * 64;       // warp n offset

    const float* xs = x + (size_t)mBase * (NSPL*DIN) + (size_t)n * DIN;
    const char*  ag = (const char*)Ah_g + (size_t)n * (DOUT*DIN) * 2;

    float acc[2][8][4];
    #pragma unroll
    for (int mb = 0; mb < 2; ++mb)
        #pragma unroll
        for (int nb = 0; nb < 8; ++nb)
            #pragma unroll
            for (int e = 0; e < 4; ++e) acc[mb][nb][e] = 0.f;

    // ldmatrix per-lane bases
    uint32_t xrb[2], xsw[2], arb[4], asw[4];
    const int kax = t8 >> 1, kaa = t8 & 1;
    #pragma unroll
    for (int mb = 0; mb < 2; ++mb){
        int row = m0w + mb*16 + (t8 & 1)*8 + r8;
        xrb[mb] = sb + XH0 + (uint32_t)row*128; xsw[mb] = row & 7;
    }
    #pragma unroll
    for (int p = 0; p < 4; ++p){
        int row = n0w + p*16 + (t8 >> 1)*8 + r8;
        arb[p] = sb + AH0 + (uint32_t)row*128; asw[p] = row & 7;
    }

    auto load_stage = [&](int s){
        const int b = s & 1;
        const int ks0 = s * KC;
        const uint32_t ahb = sb + AH0 + (uint32_t)b*32768;
        #pragma unroll
        for (int j = 0; j < 4; ++j){                 // X: 64 x 64 fp32 -> XF
            int g = tid + 256*j, row = g >> 4, c16 = g & 15;
            cpasync16(sb + XF0 + SWOFF(row, c16*16),
                      xs + (size_t)row*(NSPL*DIN) + ks0 + c16*4);
        }
        #pragma unroll
        for (int j = 0; j < 8; ++j){                 // Ah fp16: 256 rows x 64 k
            int g = tid + 256*j, row = g >> 3, c = g & 7;
            cpasync16(ahb + (uint32_t)row*128 + (uint32_t)((c ^ (row & 7)) << 4),
                      ag + ((size_t)row*DIN + ks0 + c*8)*2);
        }
        asm volatile("cp.async.commit_group;" ::: "memory");
    };

    load_stage(0);

    for (int s = 0; s < NSTG; ++s){
        const int b = s & 1;
        asm volatile("cp.async.wait_group 0;" ::: "memory");
        __syncthreads();   // stage s data visible to all warps

        // ---- convert X(s): XF -> Xh[b] (plain rn fp16) ----
        {
            const uint32_t xhb = sb + XH0 + (uint32_t)b*8192;
            #pragma unroll
            for (int j = 0; j < 4; ++j){
                int g = tid + 256*j, row = g >> 4, q = g & 15;
                float4 v = lds4(sb + XF0 + SWOFF(row, q*16));
                sts64(xhb + TQOFF(row, q),
                      cvtf16_2(make_float2(v.x, v.y)),
                      cvtf16_2(make_float2(v.z, v.w)));
            }
        }
        __syncthreads();   // tiles ready; XF free for next load

        if (s + 1 < NSTG) load_stage(s + 1);   // overlaps mainloop below

        // ---- mainloop: 4 x k16 slices, pure LDSM + HMMA ----
        const uint32_t xo = (uint32_t)b*8192, ao = (uint32_t)b*32768;
        #pragma unroll
        for (int kk = 0; kk < 4; ++kk){
            const int ck = kk*2;
            uint32_t ah[8][2];
            #pragma unroll
            for (int p = 0; p < 4; ++p){
                uint32_t addr = arb[p] + ao + (uint32_t)(((ck + kaa) ^ asw[p]) << 4);
                ldsm4(addr, ah[2*p][0], ah[2*p][1], ah[2*p+1][0], ah[2*p+1][1]);
            }
            #pragma unroll
            for (int mb = 0; mb < 2; ++mb){
                uint32_t xh[4];
                uint32_t addr = xrb[mb] + xo + (uint32_t)(((ck + kax) ^ xsw[mb]) << 4);
                ldsm4(addr, xh[0], xh[1], xh[2], xh[3]);
                #pragma unroll
                for (int nb = 0; nb < 8; ++nb)
                    mma_f16(acc[mb][nb], xh, ah[nb]);
            }
        }
    }

    // ---- epilogue: bias + STG.64 ----
    #pragma unroll
    for (int nb = 0; nb < 8; ++nb){
        const int col = n0w + nb*8 + qc*2;
        const float2 bb = *(const float2*)(Bp + (size_t)n*DOUT + col);
        #pragma unroll
        for (int mb = 0; mb < 2; ++mb){
            const int rg0 = mBase + m0w + mb*16 + qr;
            float2 v0 = make_float2(acc[mb][nb][0] + bb.x, acc[mb][nb][1] + bb.y);
            float2 v1 = make_float2(acc[mb][nb][2] + bb.x, acc[mb][nb][3] + bb.y);
            *(float2*)(out + (size_t)rg0     *(NSPL*DOUT) + (size_t)n*DOUT + col) = v0;
            *(float2*)(out + (size_t)(rg0+8) *(NSPL*DOUT) + (size_t)n*DOUT + col) = v1;
        }
    }
}

extern "C" void kernel_launch(void* const* d_in, const int* in_sizes, int n_in,
                              void* d_out, int out_size)
{
    const float* x  = (const float*)d_in[0];
    const float* A  = (const float*)d_in[1];
    const float* Bp = (const float*)d_in[2];
    float* out = (float*)d_out;

    convertA_kernel<<<8192, 256>>>(A);

    cudaFuncSetAttribute(multidense_mma, cudaFuncAttributeMaxDynamicSharedMemorySize, SMEM_TOTAL);
    dim3 grid(BSZ / BM, NSPL);   // (32, 256) = 8192 CTAs
    multidense_mma<<<grid, 256, SMEM_TOTAL>>>(x, Bp, out);
}

// round 14
// speedup vs baseline: 5.3805x; 1.0140x over previous
#include <cuda_runtime.h>
#include <cstdint>

// MultiDense y[b,n,o] = sum_i x[b,n,i]*A[n,o,i] + Bp[n,o]
// R14: pure fp16 GEMM (x ~= xh, A ~= ah), fp32 accum on mma.m16n8k16.
// X loaded via LDG.128 into regs, converted in regs (off critical path),
// STS'd directly into swizzled fp16 tile -- no fp32 smem staging.
// A pre-converted fp16 by pre-pass; cp.async double-buffered.

#define BSZ   2048
#define NSPL  256
#define DIN   256
#define DOUT  256
#define BM    64
#define KC    64
#define NSTG  4

// smem layout (bytes), per CTA = 80 KB
#define XH0   0        // Xh fp16: 2 x 8192
#define AH0   16384    // Ah fp16: 2 x 32768
#define SMEM_TOTAL 81920

// fp16 A scratch, written by pre-pass each launch
__device__ uint32_t Ah_g[(size_t)NSPL * DOUT * DIN / 2];   // 32 MB

__device__ __forceinline__ uint32_t s2u(const void* p){
    uint32_t a;
    asm("{ .reg .u64 t; cvta.to.shared.u64 t, %1; cvt.u32.u64 %0, t; }" : "=r"(a) : "l"(p));
    return a;
}
__device__ __forceinline__ void cpasync16(uint32_t s, const void* g){
    asm volatile("cp.async.cg.shared.global [%0], [%1], 16;" :: "r"(s), "l"(g));
}
__device__ __forceinline__ void sts64(uint32_t a, uint32_t v0, uint32_t v1){
    asm volatile("st.shared.v2.b32 [%0], {%1,%2};" :: "r"(a), "r"(v0), "r"(v1) : "memory");
}
__device__ __forceinline__ uint32_t cvtf16_2(float2 v){
    uint32_t h;
    asm("cvt.rn.f16x2.f32 %0, %1, %2;" : "=r"(h) : "f"(v.y), "f"(v.x));
    return h;
}
__device__ __forceinline__ void ldsm4(uint32_t a, uint32_t& r0, uint32_t& r1,
                                      uint32_t& r2, uint32_t& r3){
    asm volatile("ldmatrix.sync.aligned.m8n8.x4.shared.b16 {%0,%1,%2,%3}, [%4];"
        : "=r"(r0), "=r"(r1), "=r"(r2), "=r"(r3) : "r"(a));
}
__device__ __forceinline__ void mma_f16(float* c, const uint32_t* a, const uint32_t* b){
    asm volatile("mma.sync.aligned.m16n8k16.row.col.f32.f16.f16.f32 "
        "{%0,%1,%2,%3}, {%4,%5,%6,%7}, {%8,%9}, {%0,%1,%2,%3};"
        : "+f"(c[0]), "+f"(c[1]), "+f"(c[2]), "+f"(c[3])
        : "r"(a[0]), "r"(a[1]), "r"(a[2]), "r"(a[3]), "r"(b[0]), "r"(b[1]));
}

// fp16 tile (128B rows): 16B chunk c (0-7) XOR (row&7); q = 4-elem quad (0-15)
#define TQOFF(row, q)  ((uint32_t)((row)*128 + (((((q)>>1) ^ ((row)&7)))<<4) + ((q)&1)*8))

// ---- pre-pass: A fp32 -> fp16 scratch ----
__global__ __launch_bounds__(256, 8)
void convertA_kernel(const float* __restrict__ A){
    size_t i = (size_t)blockIdx.x * 256 + threadIdx.x;
    const float4* s = (const float4*)A + 2*i;
    float4 v0 = s[0], v1 = s[1];
    uint4 o;
    o.x = cvtf16_2(make_float2(v0.x, v0.y));
    o.y = cvtf16_2(make_float2(v0.z, v0.w));
    o.z = cvtf16_2(make_float2(v1.x, v1.y));
    o.w = cvtf16_2(make_float2(v1.z, v1.w));
    ((uint4*)Ah_g)[i] = o;
}

__global__ __launch_bounds__(256, 2)
void multidense_mma(const float* __restrict__ x,
                    const float* __restrict__ Bp, float* __restrict__ out)
{
    extern __shared__ char smem[];
    const uint32_t sb = s2u(smem);
    const int tid  = threadIdx.x;
    const int wid  = tid >> 5, lane = tid & 31;
    const int qr   = lane >> 2, qc = lane & 3;
    const int t8   = lane >> 3, r8 = lane & 7;
    const int n    = blockIdx.y;
    const int mBase= blockIdx.x * BM;
    const int m0w  = (wid >> 2) * 32;      // warp m offset (0 or 32)
    const int n0w  = (wid & 3) * 64;       // warp n offset

    // X loader mapping: 4 quads per thread, rows r0 + {0,16,32,48}, quad q = tid&15
    const int xrow0 = tid >> 4;            // 0..15
    const int xq    = tid & 15;
    const float* xg = x + (size_t)(mBase + xrow0) * (NSPL*DIN) + (size_t)n * DIN + xq*4;
    const char*  ag = (const char*)Ah_g + (size_t)n * (DOUT*DIN) * 2;

    // precomputed swizzled STS offsets for the 4 quads
    uint32_t xsts[4];
    #pragma unroll
    for (int j = 0; j < 4; ++j) xsts[j] = TQOFF(xrow0 + 16*j, xq);

    float acc[2][8][4];
    #pragma unroll
    for (int mb = 0; mb < 2; ++mb)
        #pragma unroll
        for (int nb = 0; nb < 8; ++nb)
            #pragma unroll
            for (int e = 0; e < 4; ++e) acc[mb][nb][e] = 0.f;

    // ldmatrix per-lane bases
    uint32_t xrb[2], xsw[2], arb[4], asw[4];
    const int kax = t8 >> 1, kaa = t8 & 1;
    #pragma unroll
    for (int mb = 0; mb < 2; ++mb){
        int row = m0w + mb*16 + (t8 & 1)*8 + r8;
        xrb[mb] = sb + XH0 + (uint32_t)row*128; xsw[mb] = row & 7;
    }
    #pragma unroll
    for (int p = 0; p < 4; ++p){
        int row = n0w + p*16 + (t8 >> 1)*8 + r8;
        arb[p] = sb + AH0 + (uint32_t)row*128; asw[p] = row & 7;
    }

    auto loadA = [&](int s){
        const int b = s & 1;
        const int ks0 = s * KC;
        const uint32_t ahb = sb + AH0 + (uint32_t)b*32768;
        #pragma unroll
        for (int j = 0; j < 8; ++j){                 // Ah fp16: 256 rows x 64 k
            int g = tid + 256*j, row = g >> 3, c = g & 7;
            cpasync16(ahb + (uint32_t)row*128 + (uint32_t)((c ^ (row & 7)) << 4),
                      ag + ((size_t)row*DIN + ks0 + c*8)*2);
        }
        asm volatile("cp.async.commit_group;" ::: "memory");
    };
    auto loadX = [&](int s, float4* xr){
        const int ks0 = s * KC;
        #pragma unroll
        for (int j = 0; j < 4; ++j)
            xr[j] = *(const float4*)(xg + (size_t)(16*j)*(NSPL*DIN) + ks0);
    };
    auto cvtX = [&](const float4* xr, uint32_t* xc){
        #pragma unroll
        for (int j = 0; j < 4; ++j){
            xc[2*j]   = cvtf16_2(make_float2(xr[j].x, xr[j].y));
            xc[2*j+1] = cvtf16_2(make_float2(xr[j].z, xr[j].w));
        }
    };

    // prologue: stage 0
    float4  xr[4];
    uint32_t xc[8];
    loadX(0, xr);
    loadA(0);
    cvtX(xr, xc);

    for (int s = 0; s < NSTG; ++s){
        const int b = s & 1;
        __syncthreads();                  // XH[b] free (readers of s-2 done)

        // STS converted X(s) into XH[b]
        {
            const uint32_t xhb = sb + XH0 + (uint32_t)b*8192;
            #pragma unroll
            for (int j = 0; j < 4; ++j)
                sts64(xhb + xsts[j], xc[2*j], xc[2*j+1]);
        }

        if (s + 1 < NSTG){ loadX(s + 1, xr); loadA(s + 1); }

        if (s + 1 < NSTG) asm volatile("cp.async.wait_group 1;" ::: "memory");
        else             asm volatile("cp.async.wait_group 0;" ::: "memory");
        __syncthreads();                  // XH[b] + AH[b] visible

        // ---- mainloop: 4 x k16 slices, pure LDSM + HMMA ----
        const uint32_t xo = (uint32_t)b*8192, ao = (uint32_t)b*32768;
        #pragma unroll
        for (int kk = 0; kk < 4; ++kk){
            const int ck = kk*2;
            uint32_t ah[8][2];
            #pragma unroll
            for (int p = 0; p < 4; ++p){
                uint32_t addr = arb[p] + ao + (uint32_t)(((ck + kaa) ^ asw[p]) << 4);
                ldsm4(addr, ah[2*p][0], ah[2*p][1], ah[2*p+1][0], ah[2*p+1][1]);
            }
            #pragma unroll
            for (int mb = 0; mb < 2; ++mb){
                uint32_t xh[4];
                uint32_t addr = xrb[mb] + xo + (uint32_t)(((ck + kax) ^ xsw[mb]) << 4);
                ldsm4(addr, xh[0], xh[1], xh[2], xh[3]);
                #pragma unroll
                for (int nb = 0; nb < 8; ++nb)
                    mma_f16(acc[mb][nb], xh, ah[nb]);
            }
        }

        if (s + 1 < NSTG) cvtX(xr, xc);   // off critical path (LDG hidden by mainloop)
    }

    // ---- epilogue: bias + STG.64 ----
    #pragma unroll
    for (int nb = 0; nb < 8; ++nb){
        const int col = n0w + nb*8 + qc*2;
        const float2 bb = *(const float2*)(Bp + (size_t)n*DOUT + col);
        #pragma unroll
        for (int mb = 0; mb < 2; ++mb){
            const int rg0 = mBase + m0w + mb*16 + qr;
            float2 v0 = make_float2(acc[mb][nb][0] + bb.x, acc[mb][nb][1] + bb.y);
            float2 v1 = make_float2(acc[mb][nb][2] + bb.x, acc[mb][nb][3] + bb.y);
            *(float2*)(out + (size_t)rg0     *(NSPL*DOUT) + (size_t)n*DOUT + col) = v0;
            *(float2*)(out + (size_t)(rg0+8) *(NSPL*DOUT) + (size_t)n*DOUT + col) = v1;
        }
    }
}

extern "C" void kernel_launch(void* const* d_in, const int* in_sizes, int n_in,
                              void* d_out, int out_size)
{
    const float* x  = (const float*)d_in[0];
    const float* A  = (const float*)d_in[1];
    const float* Bp = (const float*)d_in[2];
    float* out = (float*)d_out;

    convertA_kernel<<<8192, 256>>>(A);

    cudaFuncSetAttribute(multidense_mma, cudaFuncAttributeMaxDynamicSharedMemorySize, SMEM_TOTAL);
    dim3 grid(BSZ / BM, NSPL);   // (32, 256) = 8192 CTAs
    multidense_mma<<<grid, 256, SMEM_TOTAL>>>(x, Bp, out);
}